// round 4
// baseline (speedup 1.0000x reference)
#include <cuda_runtime.h>
#include <math.h>
#include <stdint.h>
#include <stddef.h>

#define B_  16384
#define D_  768
#define H_  768
#define G4_ 3072
#define KP_ 2304   // 3*768 split-K
#define E_  4
#define L_  2
#define T_  10

// GEMM tiling
#define BM 128
#define BN 256
#define BK 32
#define NSTG 3
#define APAD 36                     // 32 + 4 pad (stride ≡ 4 mod 32 -> conflict-free)
#define STAGE_F ((BM + BN) * APAD)  // floats per stage
#define STAGE_BYTES (STAGE_F * 4)
#define SMEM_DYN (NSTG * STAGE_BYTES)

// ---------------- scratch (static device globals; no allocation) ----------------
__device__ __align__(128) float g_act2 [(size_t)B_ * KP_];
__device__ __align__(128) float g_hmid2[(size_t)B_ * KP_];
__device__ __align__(128) float g_Wi2  [(size_t)G4_ * KP_];
__device__ __align__(128) float g_Wh2  [(size_t)G4_ * KP_];
__device__ __align__(128) float g_W12  [(size_t)8 * H_ * KP_];
__device__ __align__(128) float g_W22  [(size_t)8 * D_ * KP_];
__device__ float g_xWi [(size_t)B_ * G4_];
__device__ float g_gates[(size_t)B_ * G4_];
__device__ float g_c   [(size_t)B_ * H_];
__device__ float g_hsum[(size_t)B_ * H_];
__device__ float g_x0  [(size_t)B_ * H_];
__device__ float g_accA[(size_t)B_ * D_];
__device__ float g_accB[(size_t)B_ * D_];
__device__ float g_hp  [B_];
__device__ float g_rem [B_];
__device__ float g_w   [B_ * E_];

__device__ __forceinline__ float sigf(float x) { return 1.f / (1.f + expf(-x)); }

__device__ __forceinline__ float tf32r(float f) {
    uint32_t u;
    asm("cvt.rna.tf32.f32 %0, %1;" : "=r"(u) : "f"(f));
    return __uint_as_float(u);
}

__device__ __forceinline__ uint32_t s2u(const void* p) {
    uint32_t a;
    asm("{ .reg .u64 t; cvta.to.shared.u64 t, %1; cvt.u32.u64 %0, t; }" : "=r"(a) : "l"(p));
    return a;
}

__device__ __forceinline__ void mma8(float* d, const float* a, const float* b) {
    asm volatile(
        "mma.sync.aligned.m16n8k8.row.col.f32.tf32.tf32.f32 "
        "{%0,%1,%2,%3}, {%4,%5,%6,%7}, {%8,%9}, {%0,%1,%2,%3};"
        : "+f"(d[0]), "+f"(d[1]), "+f"(d[2]), "+f"(d[3])
        : "r"(__float_as_uint(a[0])), "r"(__float_as_uint(a[1])),
          "r"(__float_as_uint(a[2])), "r"(__float_as_uint(a[3])),
          "r"(__float_as_uint(b[0])), "r"(__float_as_uint(b[1])));
}

// ---------------- 3xTF32 GEMM: C[M,N] = A'[M,Kp] @ W'[N,Kp]^T ----------------
// MODE 0: C = AB^T + bias1 + bias2
// MODE 1: C = AB^T + addsrc
// MODE 2: out3 = tf32-triple(relu(AB^T + bias1))   (activation layout hi,hi,lo)
// MODE 3: C += rowscale[row*rs_stride] * (AB^T + bias1)
template<int MODE>
__global__ __launch_bounds__(256, 1)
void tgemm(const float* __restrict__ A, const float* __restrict__ W,
           float* __restrict__ C, int N, int Kp,
           const float* __restrict__ bias1, const float* __restrict__ bias2,
           const float* __restrict__ addsrc,
           const float* __restrict__ rowscale, int rs_stride,
           float* __restrict__ out3, int out3K)
{
    extern __shared__ float smem[];
    const int tid  = threadIdx.x;
    const int lane = tid & 31;
    const int wid  = tid >> 5;
    const int m0 = blockIdx.y * BM;
    const int n0 = blockIdx.x * BN;
    const int wm = (wid >> 2) * 64;   // 2 warp-rows
    const int wn = (wid & 3) * 64;    // 4 warp-cols
    const uint32_t su = s2u(smem);

    const int NCH = Kp / BK;

    auto produce = [&](int p) {
        const float* Ab = A + (size_t)m0 * Kp + (size_t)p * BK;
        const float* Bb = W + (size_t)n0 * Kp + (size_t)p * BK;
        const uint32_t sb = su + (uint32_t)(p % NSTG) * STAGE_BYTES;
        #pragma unroll
        for (int i = 0; i < 12; ++i) {
            const int g = i * 256 + tid;
            uint32_t dst;
            const float* src;
            if (g < 1024) {                         // A: 128 rows x 8 granules
                const int row = g >> 3, c = g & 7;
                dst = sb + (uint32_t)(row * (APAD * 4) + c * 16);
                src = Ab + (size_t)row * Kp + c * 4;
            } else {                                // B: 256 rows x 8 granules
                const int gg = g - 1024;
                const int row = gg >> 3, c = gg & 7;
                dst = sb + (uint32_t)(BM * (APAD * 4) + row * (APAD * 4) + c * 16);
                src = Bb + (size_t)row * Kp + c * 4;
            }
            asm volatile("cp.async.cg.shared.global [%0], [%1], 16;" :: "r"(dst), "l"(src));
        }
        asm volatile("cp.async.commit_group;" ::: "memory");
    };

    float acc[4][8][4];
    #pragma unroll
    for (int mt = 0; mt < 4; ++mt)
        #pragma unroll
        for (int nt = 0; nt < 8; ++nt)
            #pragma unroll
            for (int q = 0; q < 4; ++q) acc[mt][nt][q] = 0.f;

    produce(0);
    produce(1);

    const int r4 = lane >> 2;
    const int c4 = lane & 3;

    for (int s = 0; s < NCH; ++s) {
        asm volatile("cp.async.wait_group 1;" ::: "memory");
        __syncthreads();
        if (s + 2 < NCH) produce(s + 2);

        const float* As = smem + (s % NSTG) * STAGE_F;
        const float* Bs = As + BM * APAD;

        #pragma unroll
        for (int k8 = 0; k8 < 4; ++k8) {
            const int kc = k8 * 8 + c4;
            float a[4][4];
            #pragma unroll
            for (int mt = 0; mt < 4; ++mt) {
                const int r = wm + mt * 16 + r4;
                a[mt][0] = As[r * APAD + kc];
                a[mt][1] = As[(r + 8) * APAD + kc];
                a[mt][2] = As[r * APAD + kc + 4];
                a[mt][3] = As[(r + 8) * APAD + kc + 4];
            }
            float b[8][2];
            #pragma unroll
            for (int nt = 0; nt < 8; ++nt) {
                const int n = wn + nt * 8 + r4;
                b[nt][0] = Bs[n * APAD + kc];
                b[nt][1] = Bs[n * APAD + kc + 4];
            }
            #pragma unroll
            for (int mt = 0; mt < 4; ++mt)
                #pragma unroll
                for (int nt = 0; nt < 8; ++nt)
                    mma8(acc[mt][nt], a[mt], b[nt]);
        }
    }

    // ---------------- epilogue ----------------
    auto epi = [&](int row, int col, float v0, float v1) {
        if (MODE == 0) {
            C[(size_t)row * N + col]     = v0 + bias1[col]     + bias2[col];
            C[(size_t)row * N + col + 1] = v1 + bias1[col + 1] + bias2[col + 1];
        } else if (MODE == 1) {
            const size_t off = (size_t)row * N + col;
            C[off]     = v0 + addsrc[off];
            C[off + 1] = v1 + addsrc[off + 1];
        } else if (MODE == 2) {
            float w0 = fmaxf(v0 + bias1[col], 0.f);
            float w1 = fmaxf(v1 + bias1[col + 1], 0.f);
            const float h0 = tf32r(w0), h1 = tf32r(w1);
            const float l0 = tf32r(w0 - h0), l1 = tf32r(w1 - h1);
            float* o = out3 + (size_t)row * (3 * out3K) + col;
            o[0] = h0;             o[1] = h1;
            o[out3K] = h0;         o[out3K + 1] = h1;
            o[2 * out3K] = l0;     o[2 * out3K + 1] = l1;
        } else { // MODE 3
            const float sc = rowscale[(size_t)row * rs_stride];
            const size_t off = (size_t)row * N + col;
            C[off]     = C[off]     + sc * (v0 + bias1[col]);
            C[off + 1] = C[off + 1] + sc * (v1 + bias1[col + 1]);
        }
    };

    #pragma unroll
    for (int mt = 0; mt < 4; ++mt) {
        #pragma unroll
        for (int nt = 0; nt < 8; ++nt) {
            const int row = m0 + wm + mt * 16 + r4;
            const int col = n0 + wn + nt * 8 + c4 * 2;
            epi(row,     col, acc[mt][nt][0], acc[mt][nt][1]);
            epi(row + 8, col, acc[mt][nt][2], acc[mt][nt][3]);
        }
    }
}

// ---------------- conversion kernels ----------------
// weight layout: [hi | lo | hi], activation layout: [hi | hi | lo]
__global__ void convW(const float* __restrict__ src, float* __restrict__ dst,
                      int Nr, int K) {
    size_t i  = (size_t)blockIdx.x * blockDim.x + threadIdx.x;
    size_t n  = (size_t)Nr * K;
    size_t st = (size_t)gridDim.x * blockDim.x;
    for (; i < n; i += st) {
        const int r = (int)(i / K), k = (int)(i % K);
        const float f = src[i];
        const float hi = tf32r(f);
        const float lo = tf32r(f - hi);
        float* o = dst + (size_t)r * (3 * K);
        o[k] = hi; o[K + k] = lo; o[2 * K + k] = hi;
    }
}
__global__ void convA(const float* __restrict__ src, float* __restrict__ dst,
                      int Nr, int K) {
    size_t i  = (size_t)blockIdx.x * blockDim.x + threadIdx.x;
    size_t n  = (size_t)Nr * K;
    size_t st = (size_t)gridDim.x * blockDim.x;
    for (; i < n; i += st) {
        const int r = (int)(i / K), k = (int)(i % K);
        const float f = src[i];
        const float hi = tf32r(f);
        const float lo = tf32r(f - hi);
        float* o = dst + (size_t)r * (3 * K);
        o[k] = hi; o[K + k] = hi; o[2 * K + k] = lo;
    }
}

__global__ void fill0(float* p, size_t n) {
    size_t i  = (size_t)blockIdx.x * blockDim.x + threadIdx.x;
    size_t st = (size_t)gridDim.x * blockDim.x;
    for (; i < n; i += st) p[i] = 0.f;
}

// ---------------- fused LSTM cell: writes h as tf32 split triple ----------------
__global__ void lstm_cell(const float* __restrict__ gates,
                          const float* __restrict__ Whalt, const float* __restrict__ bhalt,
                          float* __restrict__ c, float* __restrict__ h2,
                          float* __restrict__ hsum, float* __restrict__ hp,
                          float* __restrict__ rem)
{
    const int row = blockIdx.x;
    const int tid = threadIdx.x;   // 256
    const float* gr = gates + (size_t)row * G4_;
    float* hr = h2 + (size_t)row * KP_;
    float part = 0.f;
    #pragma unroll
    for (int it = 0; it < H_ / 256; ++it) {
        const int idx = tid + it * 256;
        const float gi = gr[idx];
        const float gf = gr[H_ + idx];
        const float gg = gr[2 * H_ + idx];
        const float go = gr[3 * H_ + idx];
        const size_t o = (size_t)row * H_ + idx;
        float cv = c[o];
        cv = sigf(gf) * cv + sigf(gi) * tanhf(gg);
        const float hv = sigf(go) * tanhf(cv);
        c[o] = cv;
        const float hi = tf32r(hv);
        const float lo = tf32r(hv - hi);
        hr[idx] = hi; hr[H_ + idx] = hi; hr[2 * H_ + idx] = lo;
        hsum[o] += hv;
        part += hv * Whalt[idx];
    }
    __shared__ float red[256];
    red[tid] = part;
    __syncthreads();
    #pragma unroll
    for (int s = 128; s > 0; s >>= 1) {
        if (tid < s) red[tid] += red[tid + s];
        __syncthreads();
    }
    if (tid == 0) {
        const float y = sigf(red[0] + bhalt[0]);
        float hpv = hp[row];
        hpv = hpv + y * (1.f - hpv);
        hp[row] = hpv;
        rem[row] += 1.f - hpv;
    }
}

// ---------------- avg: fp32 x0 (for router) + tf32 triple ----------------
__global__ void avg_kernel(const float* __restrict__ hsum, const float* __restrict__ rem,
                           float* __restrict__ x0, float* __restrict__ x02)
{
    const size_t i = (size_t)blockIdx.x * blockDim.x + threadIdx.x;
    if (i < (size_t)B_ * H_) {
        const int r = (int)(i / H_), k = (int)(i % H_);
        const float v = rem[r] * hsum[i] / 10.0f;
        x0[i] = v;
        const float hi = tf32r(v);
        const float lo = tf32r(v - hi);
        float* o = x02 + (size_t)r * KP_;
        o[k] = hi; o[H_ + k] = hi; o[2 * H_ + k] = lo;
    }
}

// ---------------- router: fp32 logits -> top2 softmax weights ----------------
__global__ void router(const float* __restrict__ x, const float* __restrict__ Wg,
                       const float* __restrict__ bg, float* __restrict__ w)
{
    const int row = blockIdx.x;
    const int tid = threadIdx.x;   // 128
    const float* xr = x + (size_t)row * H_;
    float p0 = 0.f, p1 = 0.f, p2 = 0.f, p3 = 0.f;
    for (int k = tid; k < H_; k += 128) {
        const float xv = xr[k];
        p0 += xv * Wg[k];
        p1 += xv * Wg[H_ + k];
        p2 += xv * Wg[2 * H_ + k];
        p3 += xv * Wg[3 * H_ + k];
    }
    __shared__ float red[4][128];
    red[0][tid] = p0; red[1][tid] = p1; red[2][tid] = p2; red[3][tid] = p3;
    __syncthreads();
    #pragma unroll
    for (int s = 64; s > 0; s >>= 1) {
        if (tid < s) {
            #pragma unroll
            for (int e = 0; e < 4; ++e) red[e][tid] += red[e][tid + s];
        }
        __syncthreads();
    }
    if (tid == 0) {
        float lg[4];
        #pragma unroll
        for (int e = 0; e < 4; ++e) lg[e] = red[e][0] + bg[e];
        int i1 = 0; float m1 = lg[0];
        #pragma unroll
        for (int e = 1; e < 4; ++e) if (lg[e] > m1) { m1 = lg[e]; i1 = e; }
        int i2 = -1; float m2 = -3.4e38f;
        #pragma unroll
        for (int e = 0; e < 4; ++e) if (e != i1 && lg[e] > m2) { m2 = lg[e]; i2 = e; }
        const float e2 = expf(m2 - m1);
        const float s  = 1.f + e2;
        float out4[4] = {0.f, 0.f, 0.f, 0.f};
        out4[i1] = 1.f / s;
        out4[i2] = e2 / s;
        #pragma unroll
        for (int e = 0; e < 4; ++e) w[row * 4 + e] = out4[e];
    }
}

// ---------------- final LayerNorm ----------------
__global__ void layernorm(const float* __restrict__ x, const float* __restrict__ gamma,
                          const float* __restrict__ beta, float* __restrict__ out)
{
    const int row = blockIdx.x;
    const int tid = threadIdx.x;   // 256
    const float* xr = x + (size_t)row * D_;
    float v[D_ / 256];
    float s = 0.f;
    #pragma unroll
    for (int it = 0; it < D_ / 256; ++it) { v[it] = xr[tid + it * 256]; s += v[it]; }
    __shared__ float red[256];
    red[tid] = s;
    __syncthreads();
    #pragma unroll
    for (int st = 128; st > 0; st >>= 1) {
        if (tid < st) red[tid] += red[tid + st];
        __syncthreads();
    }
    const float mu = red[0] / (float)D_;
    __syncthreads();
    float s2 = 0.f;
    #pragma unroll
    for (int it = 0; it < D_ / 256; ++it) { const float d = v[it] - mu; s2 += d * d; }
    red[tid] = s2;
    __syncthreads();
    #pragma unroll
    for (int st = 128; st > 0; st >>= 1) {
        if (tid < st) red[tid] += red[tid + st];
        __syncthreads();
    }
    const float var = red[0] / (float)D_;
    const float inv = rsqrtf(var + 1e-5f);
    #pragma unroll
    for (int it = 0; it < D_ / 256; ++it) {
        const int cc = tid + it * 256;
        out[(size_t)row * D_ + cc] = (v[it] - mu) * inv * gamma[cc] + beta[cc];
    }
}

// ---------------- host ----------------
struct Ptrs {
    float *act2, *hmid2, *Wi2, *Wh2, *W12, *W22;
    float *xWi, *gates, *c, *hsum, *x0, *accA, *accB, *hp, *rem, *w;
};

static Ptrs get_ptrs() {
    static Ptrs P = [] {
        Ptrs q{};
        cudaGetSymbolAddress((void**)&q.act2,  g_act2);
        cudaGetSymbolAddress((void**)&q.hmid2, g_hmid2);
        cudaGetSymbolAddress((void**)&q.Wi2,   g_Wi2);
        cudaGetSymbolAddress((void**)&q.Wh2,   g_Wh2);
        cudaGetSymbolAddress((void**)&q.W12,   g_W12);
        cudaGetSymbolAddress((void**)&q.W22,   g_W22);
        cudaGetSymbolAddress((void**)&q.xWi,   g_xWi);
        cudaGetSymbolAddress((void**)&q.gates, g_gates);
        cudaGetSymbolAddress((void**)&q.c,     g_c);
        cudaGetSymbolAddress((void**)&q.hsum,  g_hsum);
        cudaGetSymbolAddress((void**)&q.x0,    g_x0);
        cudaGetSymbolAddress((void**)&q.accA,  g_accA);
        cudaGetSymbolAddress((void**)&q.accB,  g_accB);
        cudaGetSymbolAddress((void**)&q.hp,    g_hp);
        cudaGetSymbolAddress((void**)&q.rem,   g_rem);
        cudaGetSymbolAddress((void**)&q.w,     g_w);
        return q;
    }();
    return P;
}

extern "C" void kernel_launch(void* const* d_in, const int* in_sizes, int n_in,
                              void* d_out, int out_size)
{
    const float* x     = (const float*)d_in[0];
    const float* Wi    = (const float*)d_in[1];
    const float* Wh    = (const float*)d_in[2];
    const float* bi    = (const float*)d_in[3];
    const float* bh    = (const float*)d_in[4];
    const float* Whalt = (const float*)d_in[5];
    const float* bhalt = (const float*)d_in[6];
    const float* gateW = (const float*)d_in[7];
    const float* gateb = (const float*)d_in[8];
    const float* W1    = (const float*)d_in[9];
    const float* b1    = (const float*)d_in[10];
    const float* W2    = (const float*)d_in[11];
    const float* b2    = (const float*)d_in[12];
    const float* gamma = (const float*)d_in[13];
    const float* beta  = (const float*)d_in[14];
    float* out = (float*)d_out;

    Ptrs P = get_ptrs();

    cudaFuncSetAttribute((const void*)tgemm<0>, cudaFuncAttributeMaxDynamicSharedMemorySize, SMEM_DYN);
    cudaFuncSetAttribute((const void*)tgemm<1>, cudaFuncAttributeMaxDynamicSharedMemorySize, SMEM_DYN);
    cudaFuncSetAttribute((const void*)tgemm<2>, cudaFuncAttributeMaxDynamicSharedMemorySize, SMEM_DYN);
    cudaFuncSetAttribute((const void*)tgemm<3>, cudaFuncAttributeMaxDynamicSharedMemorySize, SMEM_DYN);

    // weight + input conversion to split-tf32
    convW<<<2048, 256>>>(Wi, P.Wi2, G4_, H_);
    convW<<<2048, 256>>>(Wh, P.Wh2, G4_, H_);
    convW<<<2048, 256>>>(W1, P.W12, 8 * H_, H_);
    convW<<<2048, 256>>>(W2, P.W22, 8 * D_, H_);
    convA<<<4096, 256>>>(x, P.act2, B_, D_);

    // zero recurrent state
    fill0<<<2048, 256>>>(P.c,    (size_t)B_ * H_);
    fill0<<<2048, 256>>>(P.hsum, (size_t)B_ * H_);
    fill0<<<64,   256>>>(P.hp,   (size_t)B_);
    fill0<<<64,   256>>>(P.rem,  (size_t)B_);

    // xWi = x @ Wi^T + bi + bh
    dim3 gridG(G4_ / BN, B_ / BM);
    tgemm<0><<<gridG, 256, SMEM_DYN>>>(P.act2, P.Wi2, P.xWi, G4_, KP_,
                                       bi, bh, nullptr, nullptr, 0, nullptr, 0);

    for (int t = 0; t < T_; ++t) {
        const float* gptr;
        if (t == 0) {
            gptr = P.xWi;   // h==0 -> gates == xWi
        } else {
            tgemm<1><<<gridG, 256, SMEM_DYN>>>(P.act2, P.Wh2, P.gates, G4_, KP_,
                                               nullptr, nullptr, P.xWi, nullptr, 0, nullptr, 0);
            gptr = P.gates;
        }
        lstm_cell<<<B_, 256>>>(gptr, Whalt, bhalt, P.c, P.act2, P.hsum, P.hp, P.rem);
    }

    avg_kernel<<<(B_ * H_ + 255) / 256, 256>>>(P.hsum, P.rem, P.x0, P.act2);

    dim3 gridH(H_ / BN, B_ / BM);
    const float* cur = P.x0;
    float* nxt = P.accA;
    for (int l = 0; l < L_; ++l) {
        router<<<B_, 128>>>(cur, gateW + (size_t)l * E_ * H_, gateb + (size_t)l * E_, P.w);
        fill0<<<2048, 256>>>(nxt, (size_t)B_ * D_);
        for (int e = 0; e < E_; ++e) {
            const size_t le = (size_t)l * E_ + e;
            tgemm<2><<<gridH, 256, SMEM_DYN>>>(P.act2, P.W12 + le * H_ * KP_, nullptr, H_, KP_,
                                               b1 + le * H_, nullptr, nullptr, nullptr, 0,
                                               P.hmid2, H_);
            tgemm<3><<<gridH, 256, SMEM_DYN>>>(P.hmid2, P.W22 + le * (size_t)D_ * KP_, nxt, D_, KP_,
                                               b2 + le * D_, nullptr, nullptr, P.w + e, E_,
                                               nullptr, 0);
        }
        if (l + 1 < L_) convA<<<4096, 256>>>(nxt, P.act2, B_, D_);
        cur = nxt;
        nxt = P.accB;
    }

    layernorm<<<B_, 256>>>(cur, gamma, beta, out);
}

// round 9
// speedup vs baseline: 2.9285x; 2.9285x over previous
#include <cuda_runtime.h>
#include <cuda_fp16.h>
#include <math.h>
#include <stdint.h>
#include <stddef.h>

#define B_  16384
#define D_  768
#define H_  768
#define G4_ 3072
#define KP_ 2304   // 3*768 split-K
#define E_  4
#define L_  2
#define T_  10

#define SCALE_  32.0f
#define INVSQ_  (1.0f / 1024.0f)

// GEMM tiling
#define BM 128
#define BN 256
#define BK 64                        // fp16 elements -> 128 bytes per row
#define NSTG 3
#define A_STAGE_BYTES (BM * 128)     // 16384
#define STAGE_BYTES ((BM + BN) * 128)
#define SMEM_DYN (NSTG * STAGE_BYTES)

// ---------------- scratch (static device globals; no allocation) ----------------
__device__ __align__(128) __half g_act2 [(size_t)B_ * KP_];
__device__ __align__(128) __half g_hmid2[(size_t)B_ * KP_];
__device__ __align__(128) __half g_Wi2  [(size_t)G4_ * KP_];
__device__ __align__(128) __half g_Wh2  [(size_t)G4_ * KP_];
__device__ __align__(128) __half g_W12  [(size_t)8 * H_ * KP_];
__device__ __align__(128) __half g_W22  [(size_t)8 * D_ * KP_];
__device__ float g_xWi [(size_t)B_ * G4_];
__device__ float g_gates[(size_t)B_ * G4_];
__device__ float g_c   [(size_t)B_ * H_];
__device__ float g_hsum[(size_t)B_ * H_];
__device__ float g_x0  [(size_t)B_ * H_];
__device__ float g_accA[(size_t)B_ * D_];
__device__ float g_accB[(size_t)B_ * D_];
__device__ float g_hp  [B_];
__device__ float g_rem [B_];
__device__ float g_w   [B_ * E_];

__device__ __forceinline__ float sigf(float x) { return 1.f / (1.f + expf(-x)); }

__device__ __forceinline__ uint32_t s2u(const void* p) {
    uint32_t a;
    asm("{ .reg .u64 t; cvta.to.shared.u64 t, %1; cvt.u32.u64 %0, t; }" : "=r"(a) : "l"(p));
    return a;
}
__device__ __forceinline__ uint32_t swz(uint32_t off) { return off ^ ((off >> 3) & 0x70); }

__device__ __forceinline__ void ldsm4(uint32_t* r, uint32_t addr) {
    asm volatile("ldmatrix.sync.aligned.m8n8.x4.shared.b16 {%0,%1,%2,%3}, [%4];"
                 : "=r"(r[0]), "=r"(r[1]), "=r"(r[2]), "=r"(r[3]) : "r"(addr));
}

__device__ __forceinline__ void mma16(float* d, const uint32_t* a, uint32_t b0, uint32_t b1) {
    asm volatile(
        "mma.sync.aligned.m16n8k16.row.col.f32.f16.f16.f32 "
        "{%0,%1,%2,%3}, {%4,%5,%6,%7}, {%8,%9}, {%0,%1,%2,%3};"
        : "+f"(d[0]), "+f"(d[1]), "+f"(d[2]), "+f"(d[3])
        : "r"(a[0]), "r"(a[1]), "r"(a[2]), "r"(a[3]), "r"(b0), "r"(b1));
}

// ---------------- fp16 split-3 GEMM: C[M,N] = A'[M,Kp] @ W'[N,Kp]^T -------------
// Operands pre-scaled by 32; accumulator scaled by 1024; epilogue applies INVSQ_.
// MODE 0: C = AB^T + bias1 + bias2
// MODE 1: C = AB^T + addsrc
// MODE 2: out3 = fp16-triple(relu(AB^T + bias1))   (activation layout hi,hi,lo)
// MODE 3: C += rowscale[row*rs_stride] * (AB^T + bias1)
template<int MODE>
__global__ __launch_bounds__(256, 1)
void tgemm(const __half* __restrict__ A, const __half* __restrict__ W,
           float* __restrict__ C, int N, int Kp,
           const float* __restrict__ bias1, const float* __restrict__ bias2,
           const float* __restrict__ addsrc,
           const float* __restrict__ rowscale, int rs_stride,
           __half* __restrict__ out3, int out3K)
{
    extern __shared__ char smem[];
    const int tid  = threadIdx.x;
    const int lane = tid & 31;
    const int wid  = tid >> 5;
    const int m0 = blockIdx.y * BM;
    const int n0 = blockIdx.x * BN;
    const int wm = (wid >> 2) * 64;   // 2 warp-rows
    const int wn = (wid & 3) * 64;    // 4 warp-cols
    const uint32_t su = s2u(smem);

    const int NCH = Kp / BK;

    auto produce = [&](int p) {
        const __half* Ab = A + (size_t)m0 * Kp + (size_t)p * BK;
        const __half* Bb = W + (size_t)n0 * Kp + (size_t)p * BK;
        const uint32_t sb = su + (uint32_t)(p % NSTG) * STAGE_BYTES;
        #pragma unroll
        for (int i = 0; i < 12; ++i) {
            const int g = i * 256 + tid;
            uint32_t dst;
            const __half* src;
            if (g < 1024) {                        // A: 128 rows x 8 16B-granules
                const int row = g >> 3, c = g & 7;
                dst = sb + swz((uint32_t)(row * 128 + c * 16));
                src = Ab + (size_t)row * Kp + c * 8;
            } else {                               // B: 256 rows x 8 granules
                const int gg = g - 1024;
                const int row = gg >> 3, c = gg & 7;
                dst = sb + A_STAGE_BYTES + swz((uint32_t)(row * 128 + c * 16));
                src = Bb + (size_t)row * Kp + c * 8;
            }
            asm volatile("cp.async.cg.shared.global [%0], [%1], 16;" :: "r"(dst), "l"(src));
        }
        asm volatile("cp.async.commit_group;" ::: "memory");
    };

    float acc[4][8][4];
    #pragma unroll
    for (int mt = 0; mt < 4; ++mt)
        #pragma unroll
        for (int nt = 0; nt < 8; ++nt)
            #pragma unroll
            for (int q = 0; q < 4; ++q) acc[mt][nt][q] = 0.f;

    produce(0);
    produce(1);

    const int lr = lane & 7;
    const int lg = lane >> 3;

    for (int s = 0; s < NCH; ++s) {
        asm volatile("cp.async.wait_group 1;" ::: "memory");
        __syncthreads();
        if (s + 2 < NCH) produce(s + 2);

        const uint32_t sb = su + (uint32_t)(s % NSTG) * STAGE_BYTES;

        #pragma unroll
        for (int kk = 0; kk < 4; ++kk) {
            uint32_t ar[4][4];
            #pragma unroll
            for (int mt = 0; mt < 4; ++mt) {
                // ldmatrix tile order: r0=(m+0..7,k lo) r1=(m+8..15,k lo) r2=(m+0..7,k hi) r3=(m+8..15,k hi)
                const int row = wm + mt * 16 + (lg & 1) * 8 + lr;
                const int c16 = 2 * kk + (lg >> 1);
                ldsm4(ar[mt], sb + swz((uint32_t)(row * 128 + c16 * 16)));
            }
            uint32_t br[4][4];
            #pragma unroll
            for (int nt2 = 0; nt2 < 4; ++nt2) {
                // tile order: r0=(n+0..7,k lo) r1=(n+0..7,k hi) r2=(n+8..15,k lo) r3=(n+8..15,k hi)
                const int row = wn + nt2 * 16 + (lg >> 1) * 8 + lr;
                const int c16 = 2 * kk + (lg & 1);
                ldsm4(br[nt2], sb + A_STAGE_BYTES + swz((uint32_t)(row * 128 + c16 * 16)));
            }
            #pragma unroll
            for (int mt = 0; mt < 4; ++mt)
                #pragma unroll
                for (int nt = 0; nt < 8; ++nt) {
                    const int nt2 = nt >> 1, hi = (nt & 1) * 2;
                    mma16(acc[mt][nt], ar[mt], br[nt2][hi], br[nt2][hi + 1]);
                }
        }
    }

    // ---------------- epilogue ----------------
    const int r4 = lane >> 2;
    const int c4 = lane & 3;

    auto epi = [&](int row, int col, float v0, float v1) {
        v0 *= INVSQ_; v1 *= INVSQ_;
        if (MODE == 0) {
            C[(size_t)row * N + col]     = v0 + bias1[col]     + bias2[col];
            C[(size_t)row * N + col + 1] = v1 + bias1[col + 1] + bias2[col + 1];
        } else if (MODE == 1) {
            const size_t off = (size_t)row * N + col;
            C[off]     = v0 + addsrc[off];
            C[off + 1] = v1 + addsrc[off + 1];
        } else if (MODE == 2) {
            float w0 = fmaxf(v0 + bias1[col], 0.f);
            float w1 = fmaxf(v1 + bias1[col + 1], 0.f);
            const __half h0 = __float2half_rn(SCALE_ * w0);
            const __half h1 = __float2half_rn(SCALE_ * w1);
            const __half l0 = __float2half_rn(SCALE_ * w0 - __half2float(h0));
            const __half l1 = __float2half_rn(SCALE_ * w1 - __half2float(h1));
            __half* o = out3 + (size_t)row * (3 * out3K) + col;
            o[0] = h0;             o[1] = h1;
            o[out3K] = h0;         o[out3K + 1] = h1;
            o[2 * out3K] = l0;     o[2 * out3K + 1] = l1;
        } else { // MODE 3
            const float sc = rowscale[(size_t)row * rs_stride];
            const size_t off = (size_t)row * N + col;
            C[off]     = C[off]     + sc * (v0 + bias1[col]);
            C[off + 1] = C[off + 1] + sc * (v1 + bias1[col + 1]);
        }
    };

    #pragma unroll
    for (int mt = 0; mt < 4; ++mt) {
        #pragma unroll
        for (int nt = 0; nt < 8; ++nt) {
            const int row = m0 + wm + mt * 16 + r4;
            const int col = n0 + wn + nt * 8 + c4 * 2;
            epi(row,     col, acc[mt][nt][0], acc[mt][nt][1]);
            epi(row + 8, col, acc[mt][nt][2], acc[mt][nt][3]);
        }
    }
}

// ---------------- conversion kernels ----------------
// weight layout: [hi | lo | hi], activation layout: [hi | hi | lo]; values x32
__global__ void convW(const float* __restrict__ src, __half* __restrict__ dst,
                      int Nr, int K) {
    size_t i  = (size_t)blockIdx.x * blockDim.x + threadIdx.x;
    size_t n  = (size_t)Nr * K;
    size_t st = (size_t)gridDim.x * blockDim.x;
    for (; i < n; i += st) {
        const int r = (int)(i / K), k = (int)(i % K);
        const float f = SCALE_ * src[i];
        const __half hi = __float2half_rn(f);
        const __half lo = __float2half_rn(f - __half2float(hi));
        __half* o = dst + (size_t)r * (3 * K);
        o[k] = hi; o[K + k] = lo; o[2 * K + k] = hi;
    }
}
__global__ void convA(const float* __restrict__ src, __half* __restrict__ dst,
                      int Nr, int K) {
    size_t i  = (size_t)blockIdx.x * blockDim.x + threadIdx.x;
    size_t n  = (size_t)Nr * K;
    size_t st = (size_t)gridDim.x * blockDim.x;
    for (; i < n; i += st) {
        const int r = (int)(i / K), k = (int)(i % K);
        const float f = SCALE_ * src[i];
        const __half hi = __float2half_rn(f);
        const __half lo = __float2half_rn(f - __half2float(hi));
        __half* o = dst + (size_t)r * (3 * K);
        o[k] = hi; o[K + k] = hi; o[2 * K + k] = lo;
    }
}

__global__ void fill0(float* p, size_t n) {
    size_t i  = (size_t)blockIdx.x * blockDim.x + threadIdx.x;
    size_t st = (size_t)gridDim.x * blockDim.x;
    for (; i < n; i += st) p[i] = 0.f;
}

// ---------------- fused LSTM cell: writes h as x32 fp16 split triple ------------
__global__ void lstm_cell(const float* __restrict__ gates,
                          const float* __restrict__ Whalt, const float* __restrict__ bhalt,
                          float* __restrict__ c, __half* __restrict__ h2,
                          float* __restrict__ hsum, float* __restrict__ hp,
                          float* __restrict__ rem)
{
    const int row = blockIdx.x;
    const int tid = threadIdx.x;   // 256
    const float* gr = gates + (size_t)row * G4_;
    __half* hr = h2 + (size_t)row * KP_;
    float part = 0.f;
    #pragma unroll
    for (int it = 0; it < H_ / 256; ++it) {
        const int idx = tid + it * 256;
        const float gi = gr[idx];
        const float gf = gr[H_ + idx];
        const float gg = gr[2 * H_ + idx];
        const float go = gr[3 * H_ + idx];
        const size_t o = (size_t)row * H_ + idx;
        float cv = c[o];
        cv = sigf(gf) * cv + sigf(gi) * tanhf(gg);
        const float hv = sigf(go) * tanhf(cv);
        c[o] = cv;
        const float f = SCALE_ * hv;
        const __half hi = __float2half_rn(f);
        const __half lo = __float2half_rn(f - __half2float(hi));
        hr[idx] = hi; hr[H_ + idx] = hi; hr[2 * H_ + idx] = lo;
        hsum[o] += hv;
        part += hv * Whalt[idx];
    }
    __shared__ float red[256];
    red[tid] = part;
    __syncthreads();
    #pragma unroll
    for (int s = 128; s > 0; s >>= 1) {
        if (tid < s) red[tid] += red[tid + s];
        __syncthreads();
    }
    if (tid == 0) {
        const float y = sigf(red[0] + bhalt[0]);
        float hpv = hp[row];
        hpv = hpv + y * (1.f - hpv);
        hp[row] = hpv;
        rem[row] += 1.f - hpv;
    }
}

// ---------------- avg: fp32 x0 (for router) + fp16 triple ----------------
__global__ void avg_kernel(const float* __restrict__ hsum, const float* __restrict__ rem,
                           float* __restrict__ x0, __half* __restrict__ x02)
{
    const size_t i = (size_t)blockIdx.x * blockDim.x + threadIdx.x;
    if (i < (size_t)B_ * H_) {
        const int r = (int)(i / H_), k = (int)(i % H_);
        const float v = rem[r] * hsum[i] / 10.0f;
        x0[i] = v;
        const float f = SCALE_ * v;
        const __half hi = __float2half_rn(f);
        const __half lo = __float2half_rn(f - __half2float(hi));
        __half* o = x02 + (size_t)r * KP_;
        o[k] = hi; o[H_ + k] = hi; o[2 * H_ + k] = lo;
    }
}

// ---------------- router: fp32 logits -> top2 softmax weights ----------------
__global__ void router(const float* __restrict__ x, const float* __restrict__ Wg,
                       const float* __restrict__ bg, float* __restrict__ w)
{
    const int row = blockIdx.x;
    const int tid = threadIdx.x;   // 128
    const float* xr = x + (size_t)row * H_;
    float p0 = 0.f, p1 = 0.f, p2 = 0.f, p3 = 0.f;
    for (int k = tid; k < H_; k += 128) {
        const float xv = xr[k];
        p0 += xv * Wg[k];
        p1 += xv * Wg[H_ + k];
        p2 += xv * Wg[2 * H_ + k];
        p3 += xv * Wg[3 * H_ + k];
    }
    __shared__ float red[4][128];
    red[0][tid] = p0; red[1][tid] = p1; red[2][tid] = p2; red[3][tid] = p3;
    __syncthreads();
    #pragma unroll
    for (int s = 64; s > 0; s >>= 1) {
        if (tid < s) {
            #pragma unroll
            for (int e = 0; e < 4; ++e) red[e][tid] += red[e][tid + s];
        }
        __syncthreads();
    }
    if (tid == 0) {
        float lg[4];
        #pragma unroll
        for (int e = 0; e < 4; ++e) lg[e] = red[e][0] + bg[e];
        int i1 = 0; float m1 = lg[0];
        #pragma unroll
        for (int e = 1; e < 4; ++e) if (lg[e] > m1) { m1 = lg[e]; i1 = e; }
        int i2 = -1; float m2 = -3.4e38f;
        #pragma unroll
        for (int e = 0; e < 4; ++e) if (e != i1 && lg[e] > m2) { m2 = lg[e]; i2 = e; }
        const float e2 = expf(m2 - m1);
        const float s  = 1.f + e2;
        float out4[4] = {0.f, 0.f, 0.f, 0.f};
        out4[i1] = 1.f / s;
        out4[i2] = e2 / s;
        #pragma unroll
        for (int e = 0; e < 4; ++e) w[row * 4 + e] = out4[e];
    }
}

// ---------------- final LayerNorm ----------------
__global__ void layernorm(const float* __restrict__ x, const float* __restrict__ gamma,
                          const float* __restrict__ beta, float* __restrict__ out)
{
    const int row = blockIdx.x;
    const int tid = threadIdx.x;   // 256
    const float* xr = x + (size_t)row * D_;
    float v[D_ / 256];
    float s = 0.f;
    #pragma unroll
    for (int it = 0; it < D_ / 256; ++it) { v[it] = xr[tid + it * 256]; s += v[it]; }
    __shared__ float red[256];
    red[tid] = s;
    __syncthreads();
    #pragma unroll
    for (int st = 128; st > 0; st >>= 1) {
        if (tid < st) red[tid] += red[tid + st];
        __syncthreads();
    }
    const float mu = red[0] / (float)D_;
    __syncthreads();
    float s2 = 0.f;
    #pragma unroll
    for (int it = 0; it < D_ / 256; ++it) { const float d = v[it] - mu; s2 += d * d; }
    red[tid] = s2;
    __syncthreads();
    #pragma unroll
    for (int st = 128; st > 0; st >>= 1) {
        if (tid < st) red[tid] += red[tid + st];
        __syncthreads();
    }
    const float var = red[0] / (float)D_;
    const float inv = rsqrtf(var + 1e-5f);
    #pragma unroll
    for (int it = 0; it < D_ / 256; ++it) {
        const int cc = tid + it * 256;
        out[(size_t)row * D_ + cc] = (v[it] - mu) * inv * gamma[cc] + beta[cc];
    }
}

// ---------------- host ----------------
struct Ptrs {
    __half *act2, *hmid2, *Wi2, *Wh2, *W12, *W22;
    float *xWi, *gates, *c, *hsum, *x0, *accA, *accB, *hp, *rem, *w;
};

static Ptrs get_ptrs() {
    static Ptrs P = [] {
        Ptrs q{};
        cudaGetSymbolAddress((void**)&q.act2,  g_act2);
        cudaGetSymbolAddress((void**)&q.hmid2, g_hmid2);
        cudaGetSymbolAddress((void**)&q.Wi2,   g_Wi2);
        cudaGetSymbolAddress((void**)&q.Wh2,   g_Wh2);
        cudaGetSymbolAddress((void**)&q.W12,   g_W12);
        cudaGetSymbolAddress((void**)&q.W22,   g_W22);
        cudaGetSymbolAddress((void**)&q.xWi,   g_xWi);
        cudaGetSymbolAddress((void**)&q.gates, g_gates);
        cudaGetSymbolAddress((void**)&q.c,     g_c);
        cudaGetSymbolAddress((void**)&q.hsum,  g_hsum);
        cudaGetSymbolAddress((void**)&q.x0,    g_x0);
        cudaGetSymbolAddress((void**)&q.accA,  g_accA);
        cudaGetSymbolAddress((void**)&q.accB,  g_accB);
        cudaGetSymbolAddress((void**)&q.hp,    g_hp);
        cudaGetSymbolAddress((void**)&q.rem,   g_rem);
        cudaGetSymbolAddress((void**)&q.w,     g_w);
        return q;
    }();
    return P;
}

extern "C" void kernel_launch(void* const* d_in, const int* in_sizes, int n_in,
                              void* d_out, int out_size)
{
    const float* x     = (const float*)d_in[0];
    const float* Wi    = (const float*)d_in[1];
    const float* Wh    = (const float*)d_in[2];
    const float* bi    = (const float*)d_in[3];
    const float* bh    = (const float*)d_in[4];
    const float* Whalt = (const float*)d_in[5];
    const float* bhalt = (const float*)d_in[6];
    const float* gateW = (const float*)d_in[7];
    const float* gateb = (const float*)d_in[8];
    const float* W1    = (const float*)d_in[9];
    const float* b1    = (const float*)d_in[10];
    const float* W2    = (const float*)d_in[11];
    const float* b2    = (const float*)d_in[12];
    const float* gamma = (const float*)d_in[13];
    const float* beta  = (const float*)d_in[14];
    float* out = (float*)d_out;

    Ptrs P = get_ptrs();

    cudaFuncSetAttribute((const void*)tgemm<0>, cudaFuncAttributeMaxDynamicSharedMemorySize, SMEM_DYN);
    cudaFuncSetAttribute((const void*)tgemm<1>, cudaFuncAttributeMaxDynamicSharedMemorySize, SMEM_DYN);
    cudaFuncSetAttribute((const void*)tgemm<2>, cudaFuncAttributeMaxDynamicSharedMemorySize, SMEM_DYN);
    cudaFuncSetAttribute((const void*)tgemm<3>, cudaFuncAttributeMaxDynamicSharedMemorySize, SMEM_DYN);

    // weight + input conversion to x32 fp16 split triples
    convW<<<2048, 256>>>(Wi, P.Wi2, G4_, H_);
    convW<<<2048, 256>>>(Wh, P.Wh2, G4_, H_);
    convW<<<2048, 256>>>(W1, P.W12, 8 * H_, H_);
    convW<<<2048, 256>>>(W2, P.W22, 8 * D_, H_);
    convA<<<4096, 256>>>(x, P.act2, B_, D_);

    // zero recurrent state
    fill0<<<2048, 256>>>(P.c,    (size_t)B_ * H_);
    fill0<<<2048, 256>>>(P.hsum, (size_t)B_ * H_);
    fill0<<<64,   256>>>(P.hp,   (size_t)B_);
    fill0<<<64,   256>>>(P.rem,  (size_t)B_);

    // xWi = x @ Wi^T + bi + bh
    dim3 gridG(G4_ / BN, B_ / BM);
    tgemm<0><<<gridG, 256, SMEM_DYN>>>(P.act2, P.Wi2, P.xWi, G4_, KP_,
                                       bi, bh, nullptr, nullptr, 0, nullptr, 0);

    for (int t = 0; t < T_; ++t) {
        const float* gptr;
        if (t == 0) {
            gptr = P.xWi;   // h==0 -> gates == xWi
        } else {
            tgemm<1><<<gridG, 256, SMEM_DYN>>>(P.act2, P.Wh2, P.gates, G4_, KP_,
                                               nullptr, nullptr, P.xWi, nullptr, 0, nullptr, 0);
            gptr = P.gates;
        }
        lstm_cell<<<B_, 256>>>(gptr, Whalt, bhalt, P.c, P.act2, P.hsum, P.hp, P.rem);
    }

    avg_kernel<<<(B_ * H_ + 255) / 256, 256>>>(P.hsum, P.rem, P.x0, P.act2);

    dim3 gridH(H_ / BN, B_ / BM);
    const float* cur = P.x0;
    float* nxt = P.accA;
    for (int l = 0; l < L_; ++l) {
        router<<<B_, 128>>>(cur, gateW + (size_t)l * E_ * H_, gateb + (size_t)l * E_, P.w);
        fill0<<<2048, 256>>>(nxt, (size_t)B_ * D_);
        for (int e = 0; e < E_; ++e) {
            const size_t le = (size_t)l * E_ + e;
            tgemm<2><<<gridH, 256, SMEM_DYN>>>(P.act2, P.W12 + le * H_ * KP_, nullptr, H_, KP_,
                                               b1 + le * H_, nullptr, nullptr, nullptr, 0,
                                               P.hmid2, H_);
            tgemm<3><<<gridH, 256, SMEM_DYN>>>(P.hmid2, P.W22 + le * (size_t)D_ * KP_, nxt, D_, KP_,
                                               b2 + le * D_, nullptr, nullptr, P.w + e, E_,
                                               nullptr, 0);
        }
        if (l + 1 < L_) convA<<<4096, 256>>>(nxt, P.act2, B_, D_);
        cur = nxt;
        nxt = P.accB;
    }

    layernorm<<<B_, 256>>>(cur, gamma, beta, out);
}